// round 15
// baseline (speedup 1.0000x reference)
#include <cuda_runtime.h>
#include <math.h>

#define BN 16
#define DD 512
#define TT 2048
#define CC 20
#define KK 7
#define FF (CC*KK)            // 140
#define PT 2048
#define TS 32                 // similarity tile
#define EPSV 1e-8f
#define BIGV 1e9f
#define THSIM 0.5f
#define THDIF 0.1f
#define SIM_BLOCKS 576

// -------- scratch (static device globals; no runtime allocation) --------
__device__ float    g_Et[(size_t)BN*DD*PT];   // transposed gathered points [b][d][p]
__device__ int      g_fg_idx[BN*FF];
__device__ int      g_slotmap[BN*TT];
__device__ int      g_sw[BN*PT];
__device__ unsigned char g_sfg[BN*PT];
__device__ unsigned char g_sbg[BN*PT];
__device__ int      g_Nb[BN];
__device__ int      g_bgcnt[BN];
__device__ int      g_sumw[BN];
__device__ int      g_tiles[BN];
__device__ unsigned g_minff[BN*PT];
__device__ unsigned g_maxfb[BN*PT];
__device__ unsigned g_minbb[BN*PT];
__device__ unsigned g_maxbf[BN*PT];
__device__ float    g_perbatch[BN];
__device__ int      g_ticket;

__device__ __forceinline__ unsigned fenc(float f) {
    unsigned u = __float_as_uint(f);
    return (u & 0x80000000u) ? ~u : (u | 0x80000000u);
}
__device__ __forceinline__ float fdec(unsigned x) {
    return (x & 0x80000000u) ? __uint_as_float(x ^ 0x80000000u) : __uint_as_float(~x);
}

// -------- single-pass top-7 with fast-path guard --------
__global__ void k_topk(const float* __restrict__ cas) {
    int c = blockIdx.x, b = blockIdx.y, tid = threadIdx.x;
    const float* row = cas + ((size_t)b * CC + c) * TT;

    float lv[KK]; int li[KK];
#pragma unroll
    for (int j = 0; j < KK; j++) { lv[j] = -INFINITY; li[j] = 0x7fffffff; }
#pragma unroll
    for (int i = 0; i < 8; i++) {
        int t = tid + i * 256;
        float cv = row[t]; int ci = t;
        // fast path: only enter the insertion chain if it beats the current 7th
        if (cv > lv[KK - 1] || (cv == lv[KK - 1] && ci < li[KK - 1])) {
#pragma unroll
            for (int j = 0; j < KK; j++) {
                bool better = (cv > lv[j]) || (cv == lv[j] && ci < li[j]);
                if (better) { float tv = lv[j]; int ti = li[j]; lv[j] = cv; li[j] = ci; cv = tv; ci = ti; }
            }
        }
    }

    __shared__ float sv[256][KK];
    __shared__ int   si[256][KK];
#pragma unroll
    for (int j = 0; j < KK; j++) { sv[tid][j] = lv[j]; si[tid][j] = li[j]; }

    for (int s = 128; s > 0; s >>= 1) {
        __syncthreads();
        if (tid < s) {
            float mv[KK]; int mi[KK];
            int ia = 0, ib = 0;
#pragma unroll
            for (int j = 0; j < KK; j++) {
                float va = sv[tid][ia],     vb = sv[tid + s][ib];
                int   xa = si[tid][ia],     xb = si[tid + s][ib];
                bool takeA = (va > vb) || (va == vb && xa < xb);
                if (takeA) { mv[j] = va; mi[j] = xa; ia++; }
                else       { mv[j] = vb; mi[j] = xb; ib++; }
            }
#pragma unroll
            for (int j = 0; j < KK; j++) { sv[tid][j] = mv[j]; si[tid][j] = mi[j]; }
        }
    }
    __syncthreads();
    if (tid < KK) g_fg_idx[b * FF + c * KK + tid] = si[0][tid];
}

// -------- prep: unique-point slots, flags, weights, reduction init --------
__global__ void k_prep(const int* __restrict__ click, const int* __restrict__ label,
                       const int* __restrict__ clsnum) {
    int b = blockIdx.x, tid = threadIdx.x;
    int cn = clsnum ? clsnum[0] : CC;
    __shared__ int w[TT];
    __shared__ int woff[8];
    __shared__ int sbase, sbg;
    for (int t = tid; t < TT; t += 256) w[t] = 0;
    unsigned encBig = fenc(BIGV), encNeg = fenc(-BIGV);
    for (int p = tid; p < PT; p += 256) {
        g_minff[b * PT + p] = encBig;
        g_maxfb[b * PT + p] = encNeg;
        g_minbb[b * PT + p] = encBig;
        g_maxbf[b * PT + p] = encNeg;
    }
    if (tid == 0) { sbase = 0; sbg = 0; }
    __syncthreads();
    for (int i = tid; i < FF; i += 256) {
        int c = i / KK;
        if (label[b * CC + c] == 1) atomicAdd(&w[g_fg_idx[b * FF + i]], 1);
    }
    __syncthreads();
    for (int chunk = 0; chunk < TT; chunk += 256) {
        int t = chunk + tid;
        int bg  = (click[b * TT + t] == cn) ? 1 : 0;
        int wt  = w[t];
        int sel = (bg || wt > 0) ? 1 : 0;
        unsigned ball = __ballot_sync(0xffffffffu, sel);
        unsigned ballbg = __ballot_sync(0xffffffffu, bg);
        int wi = tid >> 5, lane = tid & 31;
        if (lane == 0) { woff[wi] = __popc(ball); atomicAdd(&sbg, __popc(ballbg)); }
        __syncthreads();
        if (tid == 0) {
            int s = sbase;
            for (int i = 0; i < 8; i++) { int cc2 = woff[i]; woff[i] = s; s += cc2; }
            sbase = s;
        }
        __syncthreads();
        if (sel) {
            int pos = woff[wi] + __popc(ball & ((1u << lane) - 1u));
            g_slotmap[b * TT + t] = pos;
            g_sw[b * PT + pos] = wt;
            g_sfg[b * PT + pos] = (wt > 0) ? 1 : 0;
            g_sbg[b * PT + pos] = (unsigned char)bg;
        } else {
            g_slotmap[b * TT + t] = -1;
        }
        __syncthreads();
    }
    if (tid == 0) {
        int numpos = 0;
        for (int c = 0; c < CC; c++) numpos += (label[b * CC + c] == 1) ? 1 : 0;
        g_sumw[b]  = KK * numpos;
        g_bgcnt[b] = sbg;
        g_Nb[b]    = sbase;
        g_tiles[b] = (sbase + TS - 1) / TS;
    }
}

// -------- transpose-gather: 4 d-rows/block, 8 loads in flight, shared slotmap --------
__global__ void k_gatherT(const float* __restrict__ emb) {
    int b = blockIdx.y, tid = threadIdx.x;
    int d0 = blockIdx.x * 4;
    __shared__ int smap[TT];
#pragma unroll
    for (int i = 0; i < 8; i++) smap[tid + i * 256] = g_slotmap[b * TT + tid + i * 256];
    __syncthreads();

    const float4* src = (const float4*)(emb + ((size_t)b * DD + d0) * TT);
    float4 v[8];
#pragma unroll
    for (int dd = 0; dd < 4; dd++) {
#pragma unroll
        for (int it = 0; it < 2; it++)
            v[dd * 2 + it] = src[dd * (TT / 4) + tid + it * 256];
    }
    int sA[4], sB[4];
    {
        int t0 = tid * 4, t1 = (tid + 256) * 4;
#pragma unroll
        for (int j = 0; j < 4; j++) { sA[j] = smap[t0 + j]; sB[j] = smap[t1 + j]; }
    }
#pragma unroll
    for (int dd = 0; dd < 4; dd++) {
        float* dst = g_Et + ((size_t)b * DD + d0 + dd) * PT;
        float4 a = v[dd * 2], c = v[dd * 2 + 1];
        if (sA[0] >= 0) dst[sA[0]] = a.x;
        if (sA[1] >= 0) dst[sA[1]] = a.y;
        if (sA[2] >= 0) dst[sA[2]] = a.z;
        if (sA[3] >= 0) dst[sA[3]] = a.w;
        if (sB[0] >= 0) dst[sB[0]] = c.x;
        if (sB[1] >= 0) dst[sB[1]] = c.y;
        if (sB[2] >= 0) dst[sB[2]] = c.z;
        if (sB[3] >= 0) dst[sB[3]] = c.w;
    }
}

// -------- routing: per-row min/max over typed columns, atomic-merged --------
__device__ __forceinline__ void route_tile(const float acc[4][4], int b,
                                           int rowb, int colb, int Nb,
                                           int tx, int ty,
                                           const float* __restrict__ nrR,
                                           const float* __restrict__ nrC) {
    float nc[4]; int cfg[4], cbg[4];
#pragma unroll
    for (int j = 0; j < 4; j++) {
        int lc = 4 * tx + j;
        int c = colb + lc;
        bool cok = (c < Nb);
        nc[j]  = nrC[lc];
        cfg[j] = cok && g_sfg[b * PT + c];
        cbg[j] = cok && g_sbg[b * PT + c];
    }
#pragma unroll
    for (int i = 0; i < 4; i++) {
        int lr = 4 * ty + i;
        int ri = rowb + lr;
        float nr = nrR[lr];
        float vFF = BIGV, vBF = -BIGV, vFB = -BIGV, vBB = BIGV;
#pragma unroll
        for (int j = 0; j < 4; j++) {
            float cs = acc[i][j] / fmaxf(nr * nc[j], EPSV);
            if (cfg[j]) { vFF = fminf(vFF, cs); vBF = fmaxf(vBF, cs); }
            if (cbg[j]) { vFB = fmaxf(vFB, cs); vBB = fminf(vBB, cs); }
        }
#pragma unroll
        for (int m = 4; m > 0; m >>= 1) {
            vFF = fminf(vFF, __shfl_xor_sync(0xffffffffu, vFF, m));
            vBF = fmaxf(vBF, __shfl_xor_sync(0xffffffffu, vBF, m));
            vFB = fmaxf(vFB, __shfl_xor_sync(0xffffffffu, vFB, m));
            vBB = fminf(vBB, __shfl_xor_sync(0xffffffffu, vBB, m));
        }
        if (tx == 0 && ri < Nb) {
            if (g_sfg[b * PT + ri]) {
                atomicMin(&g_minff[b * PT + ri], fenc(vFF));
                atomicMax(&g_maxfb[b * PT + ri], fenc(vFB));
            }
            if (g_sbg[b * PT + ri]) {
                atomicMax(&g_maxbf[b * PT + ri], fenc(vBF));
                atomicMin(&g_minbb[b * PT + ri], fenc(vBB));
            }
        }
    }
}

// -------- fused symmetric tiled similarity:
//          64 threads, 4x4 micro, 16-dk chunks, register-prefetch double buffer --------
__global__ void __launch_bounds__(64) k_sim() {
    __shared__ float  Sa[2][16][32];        // 4 KB
    __shared__ float  Sb[2][16][32];        // 4 KB
    __shared__ float  comb[TS][TS + 1];     // 4.2 KB
    __shared__ float4 sqa4[64], sqb4[64];   // 2 KB
    __shared__ float  nrmA[TS], nrmB[TS];
    __shared__ int    s_off[BN + 1];

    int tid = threadIdx.x;
    int tx = tid & 7, ty = tid >> 3;        // compute coords; also loader coords

    if (tid == 0) {
        int off = 0;
        for (int b = 0; b < BN; b++) { s_off[b] = off; int t = g_tiles[b]; off += t * (t + 1) / 2; }
        s_off[BN] = off;
    }
    __syncthreads();
    int total = s_off[BN];

    for (int item = blockIdx.x; item < total; item += gridDim.x) {
        int b = 0;
        while (b < BN - 1 && item >= s_off[b + 1]) b++;
        int local = item - s_off[b];
        int tiles = g_tiles[b];
        int rt = 0, rem = local;
        while (rem >= tiles - rt) { rem -= tiles - rt; rt++; }
        int ct = rt + rem;
        int Nb = g_Nb[b];
        int rowb = rt * TS, colb = ct * TS;

        const float* Eb = g_Et + (size_t)b * DD * PT;
        const float* pA = Eb + rowb + tx * 4;     // + d*PT
        const float* pB = Eb + colb + tx * 4;

        float acc[4][4];
#pragma unroll
        for (int i = 0; i < 4; i++)
#pragma unroll
            for (int j = 0; j < 4; j++) acc[i][j] = 0.f;
        float4 sqa = {0.f, 0.f, 0.f, 0.f}, sqb = {0.f, 0.f, 0.f, 0.f};
        float4 A0, A1, B0, B1;

        // prologue: chunk 0 (dk slices ty and ty+8)
        A0 = *(const float4*)(pA + (size_t)ty * PT);
        A1 = *(const float4*)(pA + (size_t)(ty + 8) * PT);
        B0 = *(const float4*)(pB + (size_t)ty * PT);
        B1 = *(const float4*)(pB + (size_t)(ty + 8) * PT);
        sqa.x += A0.x * A0.x; sqa.y += A0.y * A0.y; sqa.z += A0.z * A0.z; sqa.w += A0.w * A0.w;
        sqa.x += A1.x * A1.x; sqa.y += A1.y * A1.y; sqa.z += A1.z * A1.z; sqa.w += A1.w * A1.w;
        sqb.x += B0.x * B0.x; sqb.y += B0.y * B0.y; sqb.z += B0.z * B0.z; sqb.w += B0.w * B0.w;
        sqb.x += B1.x * B1.x; sqb.y += B1.y * B1.y; sqb.z += B1.z * B1.z; sqb.w += B1.w * B1.w;
        *(float4*)&Sa[0][ty][tx * 4] = A0; *(float4*)&Sa[0][ty + 8][tx * 4] = A1;
        *(float4*)&Sb[0][ty][tx * 4] = B0; *(float4*)&Sb[0][ty + 8][tx * 4] = B1;
        __syncthreads();

#pragma unroll 1
        for (int c = 0; c < 32; c++) {
            int buf = c & 1;
            if (c < 31) {   // prefetch chunk c+1 into registers (8 independent LDG.128)
                const float* qA = pA + (size_t)((c + 1) * 16) * PT;
                const float* qB = pB + (size_t)((c + 1) * 16) * PT;
                A0 = *(const float4*)(qA + (size_t)ty * PT);
                A1 = *(const float4*)(qA + (size_t)(ty + 8) * PT);
                B0 = *(const float4*)(qB + (size_t)ty * PT);
                B1 = *(const float4*)(qB + (size_t)(ty + 8) * PT);
            }
            // compute chunk c from smem: 4x4 micro
#pragma unroll
            for (int dk = 0; dk < 16; dk++) {
                float4 a = *(const float4*)&Sa[buf][dk][ty * 4];
                float4 v = *(const float4*)&Sb[buf][dk][tx * 4];
                acc[0][0] += a.x * v.x; acc[0][1] += a.x * v.y; acc[0][2] += a.x * v.z; acc[0][3] += a.x * v.w;
                acc[1][0] += a.y * v.x; acc[1][1] += a.y * v.y; acc[1][2] += a.y * v.z; acc[1][3] += a.y * v.w;
                acc[2][0] += a.z * v.x; acc[2][1] += a.z * v.y; acc[2][2] += a.z * v.z; acc[2][3] += a.z * v.w;
                acc[3][0] += a.w * v.x; acc[3][1] += a.w * v.y; acc[3][2] += a.w * v.z; acc[3][3] += a.w * v.w;
            }
            if (c < 31) {
                sqa.x += A0.x * A0.x; sqa.y += A0.y * A0.y; sqa.z += A0.z * A0.z; sqa.w += A0.w * A0.w;
                sqa.x += A1.x * A1.x; sqa.y += A1.y * A1.y; sqa.z += A1.z * A1.z; sqa.w += A1.w * A1.w;
                sqb.x += B0.x * B0.x; sqb.y += B0.y * B0.y; sqb.z += B0.z * B0.z; sqb.w += B0.w * B0.w;
                sqb.x += B1.x * B1.x; sqb.y += B1.y * B1.y; sqb.z += B1.z * B1.z; sqb.w += B1.w * B1.w;
                __syncthreads();   // everyone done reading buf^1's previous contents
                *(float4*)&Sa[buf ^ 1][ty][tx * 4] = A0; *(float4*)&Sa[buf ^ 1][ty + 8][tx * 4] = A1;
                *(float4*)&Sb[buf ^ 1][ty][tx * 4] = B0; *(float4*)&Sb[buf ^ 1][ty + 8][tx * 4] = B1;
                __syncthreads();   // chunk c+1 visible
            }
        }

        // deposit sq partials + comb (for transposed pass)
        sqa4[tid] = sqa; sqb4[tid] = sqb;
#pragma unroll
        for (int i = 0; i < 4; i++)
#pragma unroll
            for (int j = 0; j < 4; j++)
                comb[4 * ty + i][4 * tx + j] = acc[i][j];
        __syncthreads();

        // norms: point p folded over threads t = (p>>2) + 8*j2, j2 ascending (fixed order)
        {
            int side = tid >> 5, p = tid & 31;
            int qq = p >> 2, jj = p & 3;
            const float4* srcq = side ? sqb4 : sqa4;
            float s = 0.f;
#pragma unroll
            for (int j2 = 0; j2 < 8; j2++)
                s += ((const float*)&srcq[qq + 8 * j2])[jj];
            if (side) nrmB[p] = sqrtf(s);
            else      nrmA[p] = sqrtf(s);
        }
        __syncthreads();

        // route pass 1 from registers
        route_tile(acc, b, rowb, colb, Nb, tx, ty, nrmA, nrmB);
        // route pass 2 (off-diagonal) via smem transpose
        if (rt != ct) {
            float a2[4][4];
#pragma unroll
            for (int i = 0; i < 4; i++)
#pragma unroll
                for (int j = 0; j < 4; j++)
                    a2[i][j] = comb[4 * tx + j][4 * ty + i];
            route_tile(a2, b, colb, rowb, Nb, tx, ty, nrmB, nrmA);
        }
        __syncthreads();   // protect smem before next item
    }
}

// -------- per-batch weighted means + fused final (last-block ticket) --------
__global__ void k_batch(float* __restrict__ out) {
    int b = blockIdx.x, tid = threadIdx.x;
    int Nb = g_Nb[b];
    float sff = 0.f, sfb = 0.f, sbb = 0.f, sbf = 0.f;
    for (int p = tid; p < Nb; p += 256) {
        if (g_sfg[b * PT + p]) {
            float wv = (float)g_sw[b * PT + p];
            sff += wv * fmaxf(THSIM - fdec(g_minff[b * PT + p]), 0.f);
            sfb += wv * fmaxf(fdec(g_maxfb[b * PT + p]) - THDIF, 0.f);
        }
        if (g_sbg[b * PT + p]) {
            sbb += fmaxf(THSIM - fdec(g_minbb[b * PT + p]), 0.f);
            sbf += fmaxf(fdec(g_maxbf[b * PT + p]) - THDIF, 0.f);
        }
    }
    __shared__ float r1[256], r2[256], r3[256], r4[256];
    __shared__ int s_last;
    r1[tid] = sff; r2[tid] = sfb; r3[tid] = sbb; r4[tid] = sbf;
    __syncthreads();
    for (int s = 128; s > 0; s >>= 1) {
        if (tid < s) {
            r1[tid] += r1[tid + s]; r2[tid] += r2[tid + s];
            r3[tid] += r3[tid + s]; r4[tid] += r4[tid + s];
        }
        __syncthreads();
    }
    if (tid == 0) {
        int cnt = g_bgcnt[b];
        float denf = fmaxf((float)g_sumw[b], 1.f);
        float denb = fmaxf((float)cnt, 1.f);
        float loss = r1[0] / denf + r2[0] / denf + r3[0] / denb + r4[0] / denb;
        g_perbatch[b] = (cnt > 0) ? loss : 0.f;
        __threadfence();
        int old = atomicAdd(&g_ticket, 1);
        s_last = (old == BN - 1) ? 1 : 0;
    }
    __syncthreads();
    if (s_last && tid == 0) {
        volatile float* pb = g_perbatch;
        float s = 0.f; int c = 0;
        for (int bb = 0; bb < BN; bb++) { s += pb[bb]; if (g_bgcnt[bb] > 0) c++; }
        out[0] = s / fmaxf((float)c, 1.f);
        g_ticket = 0;   // reset for next graph replay
    }
}

extern "C" void kernel_launch(void* const* d_in, const int* in_sizes, int n_in,
                              void* d_out, int out_size) {
    const float* emb    = (const float*)d_in[0];
    const float* cas    = (const float*)d_in[1];
    const int*   click  = (const int*)d_in[2];
    const int*   label  = (const int*)d_in[3];
    const int*   clsnum = (n_in >= 5) ? (const int*)d_in[4] : nullptr;

    k_topk   <<<dim3(CC, BN), 256>>>(cas);
    k_prep   <<<BN, 256>>>(click, label, clsnum);
    k_gatherT<<<dim3(DD / 4, BN), 256>>>(emb);
    k_sim    <<<SIM_BLOCKS, 64>>>();
    k_batch  <<<BN, 256>>>((float*)d_out);
}

// round 16
// speedup vs baseline: 1.2256x; 1.2256x over previous
#include <cuda_runtime.h>
#include <math.h>

#define BN 16
#define DD 512
#define TT 2048
#define CC 20
#define KK 7
#define FF (CC*KK)            // 140
#define PT 2048
#define TS 32                 // similarity tile
#define EPSV 1e-8f
#define BIGV 1e9f
#define THSIM 0.5f
#define THDIF 0.1f
#define MAXITEMS (16*2080)    // worst case: 64 tiles/batch -> 2080 sym pairs x 16
#define SIMP_BLOCKS 2368
#define COMB_BLOCKS 592

// -------- scratch (static device globals; no runtime allocation) --------
__device__ float    g_Et[(size_t)BN*DD*PT];   // transposed gathered points [b][d][p]
__device__ float    g_pacc[(size_t)MAXITEMS*4*1024];  // per-(item,slice) partial tiles
__device__ float    g_psqA[(size_t)MAXITEMS*4*32];    // per-(item,slice) row sq partials
__device__ float    g_psqB[(size_t)MAXITEMS*4*32];
__device__ int      g_fg_idx[BN*FF];
__device__ int      g_slotmap[BN*TT];
__device__ int      g_sw[BN*PT];
__device__ unsigned char g_sfg[BN*PT];
__device__ unsigned char g_sbg[BN*PT];
__device__ int      g_Nb[BN];
__device__ int      g_bgcnt[BN];
__device__ int      g_sumw[BN];
__device__ int      g_tiles[BN];
__device__ unsigned g_minff[BN*PT];
__device__ unsigned g_maxfb[BN*PT];
__device__ unsigned g_minbb[BN*PT];
__device__ unsigned g_maxbf[BN*PT];
__device__ float    g_perbatch[BN];
__device__ int      g_ticket;

__device__ __forceinline__ unsigned fenc(float f) {
    unsigned u = __float_as_uint(f);
    return (u & 0x80000000u) ? ~u : (u | 0x80000000u);
}
__device__ __forceinline__ float fdec(unsigned x) {
    return (x & 0x80000000u) ? __uint_as_float(x ^ 0x80000000u) : __uint_as_float(~x);
}

// -------- single-pass top-7 with fast-path guard --------
__global__ void k_topk(const float* __restrict__ cas) {
    int c = blockIdx.x, b = blockIdx.y, tid = threadIdx.x;
    const float* row = cas + ((size_t)b * CC + c) * TT;

    float lv[KK]; int li[KK];
#pragma unroll
    for (int j = 0; j < KK; j++) { lv[j] = -INFINITY; li[j] = 0x7fffffff; }
#pragma unroll
    for (int i = 0; i < 8; i++) {
        int t = tid + i * 256;
        float cv = row[t]; int ci = t;
        if (cv > lv[KK - 1] || (cv == lv[KK - 1] && ci < li[KK - 1])) {
#pragma unroll
            for (int j = 0; j < KK; j++) {
                bool better = (cv > lv[j]) || (cv == lv[j] && ci < li[j]);
                if (better) { float tv = lv[j]; int ti = li[j]; lv[j] = cv; li[j] = ci; cv = tv; ci = ti; }
            }
        }
    }

    __shared__ float sv[256][KK];
    __shared__ int   si[256][KK];
#pragma unroll
    for (int j = 0; j < KK; j++) { sv[tid][j] = lv[j]; si[tid][j] = li[j]; }

    for (int s = 128; s > 0; s >>= 1) {
        __syncthreads();
        if (tid < s) {
            float mv[KK]; int mi[KK];
            int ia = 0, ib = 0;
#pragma unroll
            for (int j = 0; j < KK; j++) {
                float va = sv[tid][ia],     vb = sv[tid + s][ib];
                int   xa = si[tid][ia],     xb = si[tid + s][ib];
                bool takeA = (va > vb) || (va == vb && xa < xb);
                if (takeA) { mv[j] = va; mi[j] = xa; ia++; }
                else       { mv[j] = vb; mi[j] = xb; ib++; }
            }
#pragma unroll
            for (int j = 0; j < KK; j++) { sv[tid][j] = mv[j]; si[tid][j] = mi[j]; }
        }
    }
    __syncthreads();
    if (tid < KK) g_fg_idx[b * FF + c * KK + tid] = si[0][tid];
}

// -------- prep: unique-point slots, flags, weights, reduction init --------
__global__ void k_prep(const int* __restrict__ click, const int* __restrict__ label,
                       const int* __restrict__ clsnum) {
    int b = blockIdx.x, tid = threadIdx.x;
    int cn = clsnum ? clsnum[0] : CC;
    __shared__ int w[TT];
    __shared__ int woff[8];
    __shared__ int sbase, sbg;
    for (int t = tid; t < TT; t += 256) w[t] = 0;
    unsigned encBig = fenc(BIGV), encNeg = fenc(-BIGV);
    for (int p = tid; p < PT; p += 256) {
        g_minff[b * PT + p] = encBig;
        g_maxfb[b * PT + p] = encNeg;
        g_minbb[b * PT + p] = encBig;
        g_maxbf[b * PT + p] = encNeg;
    }
    if (tid == 0) { sbase = 0; sbg = 0; }
    __syncthreads();
    for (int i = tid; i < FF; i += 256) {
        int c = i / KK;
        if (label[b * CC + c] == 1) atomicAdd(&w[g_fg_idx[b * FF + i]], 1);
    }
    __syncthreads();
    for (int chunk = 0; chunk < TT; chunk += 256) {
        int t = chunk + tid;
        int bg  = (click[b * TT + t] == cn) ? 1 : 0;
        int wt  = w[t];
        int sel = (bg || wt > 0) ? 1 : 0;
        unsigned ball = __ballot_sync(0xffffffffu, sel);
        unsigned ballbg = __ballot_sync(0xffffffffu, bg);
        int wi = tid >> 5, lane = tid & 31;
        if (lane == 0) { woff[wi] = __popc(ball); atomicAdd(&sbg, __popc(ballbg)); }
        __syncthreads();
        if (tid == 0) {
            int s = sbase;
            for (int i = 0; i < 8; i++) { int cc2 = woff[i]; woff[i] = s; s += cc2; }
            sbase = s;
        }
        __syncthreads();
        if (sel) {
            int pos = woff[wi] + __popc(ball & ((1u << lane) - 1u));
            g_slotmap[b * TT + t] = pos;
            g_sw[b * PT + pos] = wt;
            g_sfg[b * PT + pos] = (wt > 0) ? 1 : 0;
            g_sbg[b * PT + pos] = (unsigned char)bg;
        } else {
            g_slotmap[b * TT + t] = -1;
        }
        __syncthreads();
    }
    if (tid == 0) {
        int numpos = 0;
        for (int c = 0; c < CC; c++) numpos += (label[b * CC + c] == 1) ? 1 : 0;
        g_sumw[b]  = KK * numpos;
        g_bgcnt[b] = sbg;
        g_Nb[b]    = sbase;
        g_tiles[b] = (sbase + TS - 1) / TS;
    }
}

// -------- transpose-gather: 4 d-rows/block, 8 loads in flight, shared slotmap --------
__global__ void k_gatherT(const float* __restrict__ emb) {
    int b = blockIdx.y, tid = threadIdx.x;
    int d0 = blockIdx.x * 4;
    __shared__ int smap[TT];
#pragma unroll
    for (int i = 0; i < 8; i++) smap[tid + i * 256] = g_slotmap[b * TT + tid + i * 256];
    __syncthreads();

    const float4* src = (const float4*)(emb + ((size_t)b * DD + d0) * TT);
    float4 v[8];
#pragma unroll
    for (int dd = 0; dd < 4; dd++) {
#pragma unroll
        for (int it = 0; it < 2; it++)
            v[dd * 2 + it] = src[dd * (TT / 4) + tid + it * 256];
    }
    int sA[4], sB[4];
    {
        int t0 = tid * 4, t1 = (tid + 256) * 4;
#pragma unroll
        for (int j = 0; j < 4; j++) { sA[j] = smap[t0 + j]; sB[j] = smap[t1 + j]; }
    }
#pragma unroll
    for (int dd = 0; dd < 4; dd++) {
        float* dst = g_Et + ((size_t)b * DD + d0 + dd) * PT;
        float4 a = v[dd * 2], c = v[dd * 2 + 1];
        if (sA[0] >= 0) dst[sA[0]] = a.x;
        if (sA[1] >= 0) dst[sA[1]] = a.y;
        if (sA[2] >= 0) dst[sA[2]] = a.z;
        if (sA[3] >= 0) dst[sA[3]] = a.w;
        if (sB[0] >= 0) dst[sB[0]] = c.x;
        if (sB[1] >= 0) dst[sB[1]] = c.y;
        if (sB[2] >= 0) dst[sB[2]] = c.z;
        if (sB[3] >= 0) dst[sB[3]] = c.w;
    }
}

// -------- similarity PRODUCER: work item = (tile, 128-d slice), 64-thread blocks --------
__global__ void __launch_bounds__(64) k_simp() {
    __shared__ float  Sa[2][16][32];
    __shared__ float  Sb[2][16][32];
    __shared__ float4 sqa4[64], sqb4[64];
    __shared__ int    s_off[BN + 1];

    int tid = threadIdx.x;
    int tx = tid & 7, ty = tid >> 3;

    if (tid == 0) {
        int off = 0;
        for (int b = 0; b < BN; b++) { s_off[b] = off; int t = g_tiles[b]; off += t * (t + 1) / 2; }
        s_off[BN] = off;
    }
    __syncthreads();
    int totalw = s_off[BN] * 4;

    for (int widx = blockIdx.x; widx < totalw; widx += gridDim.x) {
        int item = widx >> 2, slice = widx & 3;
        int b = 0;
        while (b < BN - 1 && item >= s_off[b + 1]) b++;
        int local = item - s_off[b];
        int tiles = g_tiles[b];
        int rt = 0, rem = local;
        while (rem >= tiles - rt) { rem -= tiles - rt; rt++; }
        int ct = rt + rem;
        int rowb = rt * TS, colb = ct * TS;

        const float* Eb = g_Et + (size_t)b * DD * PT + (size_t)(slice * 128) * PT;
        const float* pA = Eb + rowb + tx * 4;
        const float* pB = Eb + colb + tx * 4;

        float acc[4][4];
#pragma unroll
        for (int i = 0; i < 4; i++)
#pragma unroll
            for (int j = 0; j < 4; j++) acc[i][j] = 0.f;
        float4 sqa = {0.f, 0.f, 0.f, 0.f}, sqb = {0.f, 0.f, 0.f, 0.f};
        float4 A0, A1, B0, B1;

        // prologue: chunk 0
        A0 = *(const float4*)(pA + (size_t)ty * PT);
        A1 = *(const float4*)(pA + (size_t)(ty + 8) * PT);
        B0 = *(const float4*)(pB + (size_t)ty * PT);
        B1 = *(const float4*)(pB + (size_t)(ty + 8) * PT);
        sqa.x += A0.x * A0.x; sqa.y += A0.y * A0.y; sqa.z += A0.z * A0.z; sqa.w += A0.w * A0.w;
        sqa.x += A1.x * A1.x; sqa.y += A1.y * A1.y; sqa.z += A1.z * A1.z; sqa.w += A1.w * A1.w;
        sqb.x += B0.x * B0.x; sqb.y += B0.y * B0.y; sqb.z += B0.z * B0.z; sqb.w += B0.w * B0.w;
        sqb.x += B1.x * B1.x; sqb.y += B1.y * B1.y; sqb.z += B1.z * B1.z; sqb.w += B1.w * B1.w;
        *(float4*)&Sa[0][ty][tx * 4] = A0; *(float4*)&Sa[0][ty + 8][tx * 4] = A1;
        *(float4*)&Sb[0][ty][tx * 4] = B0; *(float4*)&Sb[0][ty + 8][tx * 4] = B1;
        __syncthreads();

#pragma unroll 1
        for (int c = 0; c < 8; c++) {
            int buf = c & 1;
            if (c < 7) {
                const float* qA = pA + (size_t)((c + 1) * 16) * PT;
                const float* qB = pB + (size_t)((c + 1) * 16) * PT;
                A0 = *(const float4*)(qA + (size_t)ty * PT);
                A1 = *(const float4*)(qA + (size_t)(ty + 8) * PT);
                B0 = *(const float4*)(qB + (size_t)ty * PT);
                B1 = *(const float4*)(qB + (size_t)(ty + 8) * PT);
            }
#pragma unroll
            for (int dk = 0; dk < 16; dk++) {
                float4 a = *(const float4*)&Sa[buf][dk][ty * 4];
                float4 v = *(const float4*)&Sb[buf][dk][tx * 4];
                acc[0][0] += a.x * v.x; acc[0][1] += a.x * v.y; acc[0][2] += a.x * v.z; acc[0][3] += a.x * v.w;
                acc[1][0] += a.y * v.x; acc[1][1] += a.y * v.y; acc[1][2] += a.y * v.z; acc[1][3] += a.y * v.w;
                acc[2][0] += a.z * v.x; acc[2][1] += a.z * v.y; acc[2][2] += a.z * v.z; acc[2][3] += a.z * v.w;
                acc[3][0] += a.w * v.x; acc[3][1] += a.w * v.y; acc[3][2] += a.w * v.z; acc[3][3] += a.w * v.w;
            }
            if (c < 7) {
                sqa.x += A0.x * A0.x; sqa.y += A0.y * A0.y; sqa.z += A0.z * A0.z; sqa.w += A0.w * A0.w;
                sqa.x += A1.x * A1.x; sqa.y += A1.y * A1.y; sqa.z += A1.z * A1.z; sqa.w += A1.w * A1.w;
                sqb.x += B0.x * B0.x; sqb.y += B0.y * B0.y; sqb.z += B0.z * B0.z; sqb.w += B0.w * B0.w;
                sqb.x += B1.x * B1.x; sqb.y += B1.y * B1.y; sqb.z += B1.z * B1.z; sqb.w += B1.w * B1.w;
                __syncthreads();
                *(float4*)&Sa[buf ^ 1][ty][tx * 4] = A0; *(float4*)&Sa[buf ^ 1][ty + 8][tx * 4] = A1;
                *(float4*)&Sb[buf ^ 1][ty][tx * 4] = B0; *(float4*)&Sb[buf ^ 1][ty + 8][tx * 4] = B1;
                __syncthreads();
            }
        }

        // write partial tile
        float* dst = g_pacc + ((size_t)item * 4 + slice) * 1024;
#pragma unroll
        for (int i = 0; i < 4; i++) {
            float4 vv = {acc[i][0], acc[i][1], acc[i][2], acc[i][3]};
            *(float4*)&dst[(4 * ty + i) * 32 + 4 * tx] = vv;
        }

        // fold sq partials (fixed ty-order) and write per-(item,slice,point)
        sqa4[tid] = sqa; sqb4[tid] = sqb;
        __syncthreads();
        {
            int side = tid >> 5, p = tid & 31;
            int qq = p >> 2, jj = p & 3;
            const float4* srcq = side ? sqb4 : sqa4;
            float s = 0.f;
#pragma unroll
            for (int j2 = 0; j2 < 8; j2++)
                s += ((const float*)&srcq[qq + 8 * j2])[jj];
            if (side) g_psqB[((size_t)item * 4 + slice) * 32 + p] = s;
            else      g_psqA[((size_t)item * 4 + slice) * 32 + p] = s;
        }
        __syncthreads();
    }
}

// -------- routing helper: one row-quad (4 cosines) per thread --------
__device__ __forceinline__ void route_quad(const float cs[4], int b, int ri, bool rvalid,
                                           const int cfg[4], const int cbg[4], int tx) {
    float vFF = BIGV, vBF = -BIGV, vFB = -BIGV, vBB = BIGV;
#pragma unroll
    for (int j = 0; j < 4; j++) {
        if (cfg[j]) { vFF = fminf(vFF, cs[j]); vBF = fmaxf(vBF, cs[j]); }
        if (cbg[j]) { vFB = fmaxf(vFB, cs[j]); vBB = fminf(vBB, cs[j]); }
    }
#pragma unroll
    for (int m = 4; m > 0; m >>= 1) {
        vFF = fminf(vFF, __shfl_xor_sync(0xffffffffu, vFF, m));
        vBF = fmaxf(vBF, __shfl_xor_sync(0xffffffffu, vBF, m));
        vFB = fmaxf(vFB, __shfl_xor_sync(0xffffffffu, vFB, m));
        vBB = fminf(vBB, __shfl_xor_sync(0xffffffffu, vBB, m));
    }
    if (tx == 0 && rvalid) {
        if (g_sfg[b * PT + ri]) {
            atomicMin(&g_minff[b * PT + ri], fenc(vFF));
            atomicMax(&g_maxfb[b * PT + ri], fenc(vFB));
        }
        if (g_sbg[b * PT + ri]) {
            atomicMax(&g_maxbf[b * PT + ri], fenc(vBF));
            atomicMin(&g_minbb[b * PT + ri], fenc(vBB));
        }
    }
}

// -------- similarity COMBINE + routing: fixed-order fold of 4 slice partials --------
__global__ void __launch_bounds__(256) k_comb() {
    __shared__ float comb[TS][TS + 1];
    __shared__ float nrmA[TS], nrmB[TS];
    __shared__ int   s_off[BN + 1];

    int tid = threadIdx.x;
    int tx = tid & 7;

    if (tid == 0) {
        int off = 0;
        for (int b = 0; b < BN; b++) { s_off[b] = off; int t = g_tiles[b]; off += t * (t + 1) / 2; }
        s_off[BN] = off;
    }
    __syncthreads();
    int total = s_off[BN];

    for (int item = blockIdx.x; item < total; item += gridDim.x) {
        int b = 0;
        while (b < BN - 1 && item >= s_off[b + 1]) b++;
        int local = item - s_off[b];
        int tiles = g_tiles[b];
        int rt = 0, rem = local;
        while (rem >= tiles - rt) { rem -= tiles - rt; rt++; }
        int ct = rt + rem;
        int Nb = g_Nb[b];
        int rowb = rt * TS, colb = ct * TS;

        // combine partial tiles (fixed order s0,s1,s2,s3)
        {
            int r = tid >> 3, cq = (tid & 7) * 4;
            const float* base = g_pacc + (size_t)item * 4096 + r * 32 + cq;
            float4 v0 = *(const float4*)(base);
            float4 v1 = *(const float4*)(base + 1024);
            float4 v2 = *(const float4*)(base + 2048);
            float4 v3 = *(const float4*)(base + 3072);
            float4 s;
            s.x = ((v0.x + v1.x) + v2.x) + v3.x;
            s.y = ((v0.y + v1.y) + v2.y) + v3.y;
            s.z = ((v0.z + v1.z) + v2.z) + v3.z;
            s.w = ((v0.w + v1.w) + v2.w) + v3.w;
            comb[r][cq] = s.x; comb[r][cq + 1] = s.y; comb[r][cq + 2] = s.z; comb[r][cq + 3] = s.w;
        }
        // norms (fixed order s0..s3)
        if (tid < 64) {
            int side = tid >> 5, p = tid & 31;
            const float* q = (side ? g_psqB : g_psqA) + (size_t)item * 128 + p;
            float s = ((q[0] + q[32]) + q[64]) + q[96];
            if (side) nrmB[p] = sqrtf(s);
            else      nrmA[p] = sqrtf(s);
        }
        __syncthreads();

        // route pass 1: rows = A-points, cols = B-points
        {
            int lr = tid >> 3;
            int ri = rowb + lr;
            float nr = nrmA[lr];
            float cs[4]; int cfg[4], cbg[4];
#pragma unroll
            for (int j = 0; j < 4; j++) {
                int lc = 4 * tx + j;
                int c = colb + lc;
                bool cok = (c < Nb);
                cs[j] = comb[lr][lc] / fmaxf(nr * nrmB[lc], EPSV);
                cfg[j] = cok && g_sfg[b * PT + c];
                cbg[j] = cok && g_sbg[b * PT + c];
            }
            route_quad(cs, b, ri, ri < Nb, cfg, cbg, tx);
        }
        // route pass 2 (off-diagonal): rows = B-points, cols = A-points
        if (rt != ct) {
            int lr = tid >> 3;
            int ri = colb + lr;
            float nr = nrmB[lr];
            float cs[4]; int cfg[4], cbg[4];
#pragma unroll
            for (int j = 0; j < 4; j++) {
                int lc = 4 * tx + j;
                int c = rowb + lc;
                bool cok = (c < Nb);
                cs[j] = comb[lc][lr] / fmaxf(nr * nrmA[lc], EPSV);
                cfg[j] = cok && g_sfg[b * PT + c];
                cbg[j] = cok && g_sbg[b * PT + c];
            }
            route_quad(cs, b, ri, ri < Nb, cfg, cbg, tx);
        }
        __syncthreads();
    }
}

// -------- per-batch weighted means + fused final (last-block ticket) --------
__global__ void k_batch(float* __restrict__ out) {
    int b = blockIdx.x, tid = threadIdx.x;
    int Nb = g_Nb[b];
    float sff = 0.f, sfb = 0.f, sbb = 0.f, sbf = 0.f;
    for (int p = tid; p < Nb; p += 256) {
        if (g_sfg[b * PT + p]) {
            float wv = (float)g_sw[b * PT + p];
            sff += wv * fmaxf(THSIM - fdec(g_minff[b * PT + p]), 0.f);
            sfb += wv * fmaxf(fdec(g_maxfb[b * PT + p]) - THDIF, 0.f);
        }
        if (g_sbg[b * PT + p]) {
            sbb += fmaxf(THSIM - fdec(g_minbb[b * PT + p]), 0.f);
            sbf += fmaxf(fdec(g_maxbf[b * PT + p]) - THDIF, 0.f);
        }
    }
    __shared__ float r1[256], r2[256], r3[256], r4[256];
    __shared__ int s_last;
    r1[tid] = sff; r2[tid] = sfb; r3[tid] = sbb; r4[tid] = sbf;
    __syncthreads();
    for (int s = 128; s > 0; s >>= 1) {
        if (tid < s) {
            r1[tid] += r1[tid + s]; r2[tid] += r2[tid + s];
            r3[tid] += r3[tid + s]; r4[tid] += r4[tid + s];
        }
        __syncthreads();
    }
    if (tid == 0) {
        int cnt = g_bgcnt[b];
        float denf = fmaxf((float)g_sumw[b], 1.f);
        float denb = fmaxf((float)cnt, 1.f);
        float loss = r1[0] / denf + r2[0] / denf + r3[0] / denb + r4[0] / denb;
        g_perbatch[b] = (cnt > 0) ? loss : 0.f;
        __threadfence();
        int old = atomicAdd(&g_ticket, 1);
        s_last = (old == BN - 1) ? 1 : 0;
    }
    __syncthreads();
    if (s_last && tid == 0) {
        volatile float* pb = g_perbatch;
        float s = 0.f; int c = 0;
        for (int bb = 0; bb < BN; bb++) { s += pb[bb]; if (g_bgcnt[bb] > 0) c++; }
        out[0] = s / fmaxf((float)c, 1.f);
        g_ticket = 0;   // reset for next graph replay
    }
}

extern "C" void kernel_launch(void* const* d_in, const int* in_sizes, int n_in,
                              void* d_out, int out_size) {
    const float* emb    = (const float*)d_in[0];
    const float* cas    = (const float*)d_in[1];
    const int*   click  = (const int*)d_in[2];
    const int*   label  = (const int*)d_in[3];
    const int*   clsnum = (n_in >= 5) ? (const int*)d_in[4] : nullptr;

    k_topk   <<<dim3(CC, BN), 256>>>(cas);
    k_prep   <<<BN, 256>>>(click, label, clsnum);
    k_gatherT<<<dim3(DD / 4, BN), 256>>>(emb);
    k_simp   <<<SIMP_BLOCKS, 64>>>();
    k_comb   <<<COMB_BLOCKS, 256>>>();
    k_batch  <<<BN, 256>>>((float*)d_out);
}